// round 7
// baseline (speedup 1.0000x reference)
#include <cuda_runtime.h>

// NECTAR binning — warp-streaming bands with 2-stage row software pipeline.
// logits [16,4,512,512] f32, val_freqs [4,9,15] f32 -> out [16,4,512,512] f32.

#define H_DIM 512
#define W_DIM 512
#define HW    (H_DIM * W_DIM)
#define NTH   128                    // 4 warps; warp = 128x8 band

struct RowData {
    float4 A, B, C, D;               // 4 px x 4 classes
    float  h0, h1, h2, h3;           // halo column (lanes 0/31 only)
};

__device__ __forceinline__ unsigned int argmax_w(float l0, float l1, float l2, float l3,
                                                 float& m) {
    m = l0; unsigned int w = 1u;
    if (l1 > m) { m = l1; w = 1u << 8;  }
    if (l2 > m) { m = l2; w = 1u << 16; }
    if (l3 > m) { m = l3; w = 1u << 24; }
    return w;
}

__device__ __forceinline__ RowData load_row(const float* __restrict__ pb, int gy,
                                            bool haloOk, int haloDx) {
    RowData d;
    const float* pr = pb + (unsigned)gy * W_DIM;
    d.A = *(const float4*)(pr);
    d.B = *(const float4*)(pr + HW);
    d.C = *(const float4*)(pr + 2 * HW);
    d.D = *(const float4*)(pr + 3 * HW);
    d.h0 = d.h1 = d.h2 = d.h3 = 0.0f;
    if (haloOk) {
        const float* hp = pr + haloDx;
        d.h0 = __ldg(hp);
        d.h1 = __ldg(hp + HW);
        d.h2 = __ldg(hp + 2 * HW);
        d.h3 = __ldg(hp + 3 * HW);
    }
    return d;
}

// contributions only (halo rows)
__device__ __forceinline__ void proc_cw(const RowData& d, bool haloOk,
                                        unsigned int cw[4], unsigned int& hw_) {
    const float p0[4] = {d.A.x, d.A.y, d.A.z, d.A.w};
    const float p1[4] = {d.B.x, d.B.y, d.B.z, d.B.w};
    const float p2[4] = {d.C.x, d.C.y, d.C.z, d.C.w};
    const float p3[4] = {d.D.x, d.D.y, d.D.z, d.D.w};
    float m;
    #pragma unroll
    for (int j = 0; j < 4; j++)
        cw[j] = argmax_w(p0[j], p1[j], p2[j], p3[j], m);
    hw_ = haloOk ? argmax_w(d.h0, d.h1, d.h2, d.h3, m) : 0u;
}

// contributions + packed bins (guarded fast exp)
__device__ __forceinline__ void proc_full(const RowData& d, bool haloOk,
                                          unsigned int cw[4], unsigned int binw[4],
                                          unsigned int& hw_) {
    const float p0[4] = {d.A.x, d.A.y, d.A.z, d.A.w};
    const float p1[4] = {d.B.x, d.B.y, d.B.z, d.B.w};
    const float p2[4] = {d.C.x, d.C.y, d.C.z, d.C.w};
    const float p3[4] = {d.D.x, d.D.y, d.D.z, d.D.w};
    const float bw = 1.0f / 15.0f;

    #pragma unroll
    for (int j = 0; j < 4; j++) {
        const float l0 = p0[j], l1 = p1[j], l2 = p2[j], l3 = p3[j];
        float m;
        cw[j] = argmax_w(l0, l1, l2, l3, m);

        const float e0 = __expf(l0);
        const float e1 = __expf(l1);
        const float e2 = __expf(l2);
        const float e3 = __expf(l3);
        const float s  = e0 + e1 + e2 + e3;
        const float tt = __fdividef(15.0f, s);
        const float u0 = e0 * tt, u1 = e1 * tt, u2 = e2 * tt, u3 = e3 * tt;
        int b0 = (int)u0, b1 = (int)u1, b2 = (int)u2, b3 = (int)u3;

        const float g = 2e-4f;
        const bool risky =
            (fabsf(u0 - rintf(u0)) < g) | (fabsf(u1 - rintf(u1)) < g) |
            (fabsf(u2 - rintf(u2)) < g) | (fabsf(u3 - rintf(u3)) < g);
        if (risky) {
            const float a0 = expf(l0 - m);
            const float a1 = expf(l1 - m);
            const float a2 = expf(l2 - m);
            const float a3 = expf(l3 - m);
            const float as = a0 + a1 + a2 + a3;
            const float at = (1.0f / as) / bw;
            b0 = (int)(a0 * at);
            b1 = (int)(a1 * at);
            b2 = (int)(a2 * at);
            b3 = (int)(a3 * at);
        }
        b0 = b0 > 14 ? 14 : b0;
        b1 = b1 > 14 ? 14 : b1;
        b2 = b2 > 14 ? 14 : b2;
        b3 = b3 > 14 ? 14 : b3;
        binw[j] = (unsigned)b0 | ((unsigned)b1 << 8) |
                  ((unsigned)b2 << 16) | ((unsigned)b3 << 24);
    }
    float m;
    hw_ = haloOk ? argmax_w(d.h0, d.h1, d.h2, d.h3, m) : 0u;
}

__device__ __forceinline__ void hwin(const unsigned int cw[4], unsigned int hw_,
                                     int lane, unsigned int W3[4]) {
    unsigned int prev = __shfl_up_sync(0xffffffffu, cw[3], 1);
    if (lane == 0)  prev = hw_;
    unsigned int nxt  = __shfl_down_sync(0xffffffffu, cw[0], 1);
    if (lane == 31) nxt = hw_;
    const unsigned int p01 = cw[0] + cw[1];
    const unsigned int p23 = cw[2] + cw[3];
    W3[0] = prev  + p01;
    W3[1] = p01   + cw[2];
    W3[2] = cw[1] + p23;
    W3[3] = p23   + nxt;
}

__device__ __forceinline__ void emit_row(float* __restrict__ po,
                                         const unsigned int S[4], const unsigned int W3[4],
                                         const unsigned int binsp[4],
                                         const float* __restrict__ s_vf) {
    float o0[4], o1[4], o2[4], o3[4];
    #pragma unroll
    for (int j = 0; j < 4; j++) {
        const unsigned int acc = S[j] + W3[j];
        const unsigned int idx = acc * 15u + binsp[j];   // per-byte 15*cnt+bin <= 134
        const float f0 = s_vf[        ( idx         & 0xFFu)];
        const float f1 = s_vf[135u + ((idx >> 8)    & 0xFFu)];
        const float f2 = s_vf[270u + ((idx >> 16)   & 0xFFu)];
        const float f3 = s_vf[405u + ( idx >> 24          )];
        float s = f0 + f1 + f2 + f3;
        s = (s == 0.0f) ? 1.0f : s;
        const float inv = 1.0f / s;
        o0[j] = f0 * inv; o1[j] = f1 * inv; o2[j] = f2 * inv; o3[j] = f3 * inv;
    }
    *(float4*)(po)          = make_float4(o0[0], o0[1], o0[2], o0[3]);
    *(float4*)(po + HW)     = make_float4(o1[0], o1[1], o1[2], o1[3]);
    *(float4*)(po + 2 * HW) = make_float4(o2[0], o2[1], o2[2], o2[3]);
    *(float4*)(po + 3 * HW) = make_float4(o3[0], o3[1], o3[2], o3[3]);
}

__global__ __launch_bounds__(NTH, 7)     // cap regs ~73 -> 7 CTAs/SM, single wave
void nectar_binning_kernel(const float* __restrict__ logits,
                           const float* __restrict__ val_freqs,
                           float* __restrict__ out)
{
    __shared__ float s_vf[540];
    const int tid  = threadIdx.x;
    const int lane = tid & 31;
    const int wrp  = tid >> 5;

    for (int i = tid; i < 540; i += NTH) s_vf[i] = val_freqs[i];
    __syncthreads();

    const int x0    = blockIdx.x * 128;
    const int ybase = (blockIdx.y * 4 + wrp) * 8;
    const unsigned int boff = blockIdx.z * 4u * HW;

    const float* pb = logits + boff + (unsigned)x0 + 4u * (unsigned)lane;
    float*       ob = out    + boff + (unsigned)x0 + 4u * (unsigned)lane;

    const bool edgeLane = (lane == 0) | (lane == 31);
    const bool haloOk   = edgeLane & ((lane == 0) ? (x0 > 0) : (x0 + 128 < W_DIM));
    const int  haloDx   = (lane == 0) ? -1 : 4;

    unsigned int cw[4], binw[4], W3p[4], W3[4], S[4], binsp[4];
    unsigned int hw_;

    // ---- prologue: row -1 (cw-only) and prefetch row 0 ----
    {
        const bool vtop = (ybase > 0);
        RowData rtop;
        if (vtop) rtop = load_row(pb, ybase - 1, haloOk, haloDx);
        RowData cur = load_row(pb, ybase, haloOk, haloDx);   // row 0 in flight

        if (vtop) {
            proc_cw(rtop, haloOk, cw, hw_);
            hwin(cw, hw_, lane, W3p);
        } else {
            W3p[0] = W3p[1] = W3p[2] = W3p[3] = 0u;
        }

        // ---- row 0: prefetch row 1, process row 0 ----
        RowData nxt = load_row(pb, ybase + 1, haloOk, haloDx);
        proc_full(cur, haloOk, cw, binw, hw_);
        hwin(cw, hw_, lane, W3);
        #pragma unroll
        for (int j = 0; j < 4; j++) {
            S[j]     = W3p[j] + (W3[j] - cw[j]);
            W3p[j]   = W3[j];
            binsp[j] = binw[j];
        }
        cur = nxt;

        // ---- rows 1..7: prefetch r+1, process r, emit r-1 ----
        #pragma unroll 1
        for (int r = 1; r <= 7; ++r) {
            const int gy = ybase + r;
            const bool nv = (r < 7) | (gy + 1 < H_DIM);      // row r+1 valid?
            RowData nx;
            if (nv) nx = load_row(pb, gy + 1, haloOk, haloDx);

            proc_full(cur, haloOk, cw, binw, hw_);
            hwin(cw, hw_, lane, W3);
            emit_row(ob + (unsigned)(gy - 1) * W_DIM, S, W3, binsp, s_vf);
            #pragma unroll
            for (int j = 0; j < 4; j++) {
                S[j]     = W3p[j] + (W3[j] - cw[j]);
                W3p[j]   = W3[j];
                binsp[j] = binw[j];
            }
            if (nv) cur = nx;
            else { cur.A = cur.B = cur.C = cur.D = make_float4(0, 0, 0, 0);
                   cur.h0 = cur.h1 = cur.h2 = cur.h3 = 0.0f; }
        }

        // ---- row 8 (cw-only, zeros if off-image) + emit row 7 ----
        const bool vbot = (ybase + 8 < H_DIM);
        if (vbot) {
            proc_cw(cur, haloOk, cw, hw_);
        } else {
            cw[0] = cw[1] = cw[2] = cw[3] = 0u; hw_ = 0u;
        }
        hwin(cw, hw_, lane, W3);
        emit_row(ob + (unsigned)(ybase + 7) * W_DIM, S, W3, binsp, s_vf);
    }
}

extern "C" void kernel_launch(void* const* d_in, const int* in_sizes, int n_in,
                              void* d_out, int out_size)
{
    const float* logits    = (const float*)d_in[0];
    const float* val_freqs = (const float*)d_in[1];
    float*       out       = (float*)d_out;

    const int B = in_sizes[0] / (4 * HW);        // 16

    dim3 grid(W_DIM / 128, 16, B);               // 1024 CTAs
    nectar_binning_kernel<<<grid, NTH>>>(logits, val_freqs, out);
}

// round 8
// speedup vs baseline: 1.1698x; 1.1698x over previous
#include <cuda_runtime.h>

// NECTAR binning — warp-streaming bands (R5 structure) + L2 prefetch of next
// row + streaming stores. logits [16,4,512,512] f32, val_freqs [4,9,15] f32.

#define H_DIM 512
#define W_DIM 512
#define HW    (H_DIM * W_DIM)
#define NTH   128                    // 4 warps; warp = 128x8 band

__device__ __forceinline__ unsigned int argmax_w(float l0, float l1, float l2, float l3,
                                                 float& m) {
    m = l0; unsigned int w = 1u;
    if (l1 > m) { m = l1; w = 1u << 8;  }
    if (l2 > m) { m = l2; w = 1u << 16; }
    if (l3 > m) { m = l3; w = 1u << 24; }
    return w;
}

__device__ __forceinline__ void l2_prefetch_row(const float* __restrict__ pr) {
    asm volatile("prefetch.global.L2 [%0];" :: "l"(pr));
    asm volatile("prefetch.global.L2 [%0];" :: "l"(pr + HW));
    asm volatile("prefetch.global.L2 [%0];" :: "l"(pr + 2 * HW));
    asm volatile("prefetch.global.L2 [%0];" :: "l"(pr + 3 * HW));
}

// contributions-only row (halo rows -1 / 8)
__device__ __forceinline__ void row_cw(const float* __restrict__ pr, unsigned int cw[4]) {
    const float4 A  = *(const float4*)(pr);
    const float4 Bv = *(const float4*)(pr + HW);
    const float4 Cv = *(const float4*)(pr + 2 * HW);
    const float4 Dv = *(const float4*)(pr + 3 * HW);
    const float p0[4] = {A.x, A.y, A.z, A.w};
    const float p1[4] = {Bv.x, Bv.y, Bv.z, Bv.w};
    const float p2[4] = {Cv.x, Cv.y, Cv.z, Cv.w};
    const float p3[4] = {Dv.x, Dv.y, Dv.z, Dv.w};
    float m;
    #pragma unroll
    for (int j = 0; j < 4; j++)
        cw[j] = argmax_w(p0[j], p1[j], p2[j], p3[j], m);
}

// full row: contributions + packed bins (guarded fast exp)
__device__ __forceinline__ void row_full(const float* __restrict__ pr,
                                         unsigned int cw[4], unsigned int binw[4]) {
    const float4 A  = *(const float4*)(pr);
    const float4 Bv = *(const float4*)(pr + HW);
    const float4 Cv = *(const float4*)(pr + 2 * HW);
    const float4 Dv = *(const float4*)(pr + 3 * HW);
    const float p0[4] = {A.x, A.y, A.z, A.w};
    const float p1[4] = {Bv.x, Bv.y, Bv.z, Bv.w};
    const float p2[4] = {Cv.x, Cv.y, Cv.z, Cv.w};
    const float p3[4] = {Dv.x, Dv.y, Dv.z, Dv.w};
    const float bw = 1.0f / 15.0f;

    #pragma unroll
    for (int j = 0; j < 4; j++) {
        const float l0 = p0[j], l1 = p1[j], l2 = p2[j], l3 = p3[j];
        float m;
        cw[j] = argmax_w(l0, l1, l2, l3, m);

        // fast path (no max-subtract; mathematically identical softmax)
        const float e0 = __expf(l0);
        const float e1 = __expf(l1);
        const float e2 = __expf(l2);
        const float e3 = __expf(l3);
        const float s  = e0 + e1 + e2 + e3;
        const float tt = __fdividef(15.0f, s);
        const float u0 = e0 * tt, u1 = e1 * tt, u2 = e2 * tt, u3 = e3 * tt;
        int b0 = (int)u0, b1 = (int)u1, b2 = (int)u2, b3 = (int)u3;

        const float g = 1e-4f;   // fast-path |u| error bound ~2.3e-5 -> 4x margin
        const bool risky =
            (fabsf(u0 - rintf(u0)) < g) | (fabsf(u1 - rintf(u1)) < g) |
            (fabsf(u2 - rintf(u2)) < g) | (fabsf(u3 - rintf(u3)) < g);
        if (risky) {
            // exact path: bit-validated reference formula (rel_err == 0)
            const float a0 = expf(l0 - m);
            const float a1 = expf(l1 - m);
            const float a2 = expf(l2 - m);
            const float a3 = expf(l3 - m);
            const float as = a0 + a1 + a2 + a3;
            const float at = (1.0f / as) / bw;
            b0 = (int)(a0 * at);
            b1 = (int)(a1 * at);
            b2 = (int)(a2 * at);
            b3 = (int)(a3 * at);
        }
        b0 = b0 > 14 ? 14 : b0;
        b1 = b1 > 14 ? 14 : b1;
        b2 = b2 > 14 ? 14 : b2;
        b3 = b3 > 14 ? 14 : b3;
        binw[j] = (unsigned)b0 | ((unsigned)b1 << 8) |
                  ((unsigned)b2 << 16) | ((unsigned)b3 << 24);
    }
}

__device__ __forceinline__ unsigned int halo_w(const float* __restrict__ pb,
                                               int gy, bool doit, int dx) {
    if (!doit) return 0u;
    const float* hp = pb + (unsigned)gy * W_DIM + dx;
    const float l0 = __ldg(hp);
    const float l1 = __ldg(hp + HW);
    const float l2 = __ldg(hp + 2 * HW);
    const float l3 = __ldg(hp + 3 * HW);
    float m;
    return argmax_w(l0, l1, l2, l3, m);
}

__device__ __forceinline__ void hwin(const unsigned int cw[4], unsigned int hw_,
                                     int lane, unsigned int W3[4]) {
    unsigned int prev = __shfl_up_sync(0xffffffffu, cw[3], 1);
    if (lane == 0)  prev = hw_;
    unsigned int nxt  = __shfl_down_sync(0xffffffffu, cw[0], 1);
    if (lane == 31) nxt = hw_;
    const unsigned int p01 = cw[0] + cw[1];
    const unsigned int p23 = cw[2] + cw[3];
    W3[0] = prev  + p01;
    W3[1] = p01   + cw[2];
    W3[2] = cw[1] + p23;
    W3[3] = p23   + nxt;
}

__device__ __forceinline__ void emit_row(float* __restrict__ po,
                                         const unsigned int S[4], const unsigned int W3[4],
                                         const unsigned int binsp[4],
                                         const float* __restrict__ s_vf) {
    float o0[4], o1[4], o2[4], o3[4];
    #pragma unroll
    for (int j = 0; j < 4; j++) {
        const unsigned int acc = S[j] + W3[j];
        const unsigned int idx = acc * 15u + binsp[j];   // per-byte 15*cnt+bin <= 134
        const float f0 = s_vf[        ( idx         & 0xFFu)];
        const float f1 = s_vf[135u + ((idx >> 8)    & 0xFFu)];
        const float f2 = s_vf[270u + ((idx >> 16)   & 0xFFu)];
        const float f3 = s_vf[405u + ( idx >> 24          )];
        float s = f0 + f1 + f2 + f3;
        s = (s == 0.0f) ? 1.0f : s;
        const float inv = 1.0f / s;
        o0[j] = f0 * inv; o1[j] = f1 * inv; o2[j] = f2 * inv; o3[j] = f3 * inv;
    }
    __stcs((float4*)(po),          make_float4(o0[0], o0[1], o0[2], o0[3]));
    __stcs((float4*)(po + HW),     make_float4(o1[0], o1[1], o1[2], o1[3]));
    __stcs((float4*)(po + 2 * HW), make_float4(o2[0], o2[1], o2[2], o2[3]));
    __stcs((float4*)(po + 3 * HW), make_float4(o3[0], o3[1], o3[2], o3[3]));
}

__global__ __launch_bounds__(NTH, 7)
void nectar_binning_kernel(const float* __restrict__ logits,
                           const float* __restrict__ val_freqs,
                           float* __restrict__ out)
{
    __shared__ float s_vf[540];
    const int tid  = threadIdx.x;
    const int lane = tid & 31;
    const int wrp  = tid >> 5;

    for (int i = tid; i < 540; i += NTH) s_vf[i] = val_freqs[i];
    __syncthreads();

    const int x0    = blockIdx.x * 128;
    const int ybase = (blockIdx.y * 4 + wrp) * 8;
    const unsigned int boff = blockIdx.z * 4u * HW;

    const float* pb = logits + boff + (unsigned)x0 + 4u * (unsigned)lane;
    float*       ob = out    + boff + (unsigned)x0 + 4u * (unsigned)lane;

    const bool edgeLane = (lane == 0) | (lane == 31);
    const bool haloOk   = edgeLane & ((lane == 0) ? (x0 > 0) : (x0 + 128 < W_DIM));
    const int  haloDx   = (lane == 0) ? -1 : 4;

    unsigned int cw[4], binw[4], W3p[4], W3[4], S[4], binsp[4];

    // ---- row -1 (top halo, contributions only); prefetch rows 0,1 to L2 ----
    {
        l2_prefetch_row(pb + (unsigned)ybase * W_DIM);
        l2_prefetch_row(pb + (unsigned)(ybase + 1) * W_DIM);
        const int gy = ybase - 1;
        const bool v = (gy >= 0);
        if (v) row_cw(pb + (unsigned)gy * W_DIM, cw);
        else { cw[0] = cw[1] = cw[2] = cw[3] = 0u; }
        const unsigned int hw_ = halo_w(pb, gy, haloOk & v, haloDx);
        hwin(cw, hw_, lane, W3p);
    }

    // ---- row 0 (full); prefetch row 2 ----
    {
        l2_prefetch_row(pb + (unsigned)(ybase + 2) * W_DIM);
        row_full(pb + (unsigned)ybase * W_DIM, cw, binw);
        const unsigned int hw_ = halo_w(pb, ybase, haloOk, haloDx);
        hwin(cw, hw_, lane, W3);
        #pragma unroll
        for (int j = 0; j < 4; j++) {
            S[j]     = W3p[j] + (W3[j] - cw[j]);
            W3p[j]   = W3[j];
            binsp[j] = binw[j];
        }
    }

    // ---- rows 1..7 (full; each emits row r-1; prefetch row r+2) ----
    #pragma unroll 1
    for (int r = 1; r <= 7; ++r) {
        const int gy = ybase + r;
        const int pf = (gy + 2 <= H_DIM - 1) ? (gy + 2) : (H_DIM - 1);
        l2_prefetch_row(pb + (unsigned)pf * W_DIM);
        row_full(pb + (unsigned)gy * W_DIM, cw, binw);
        const unsigned int hw_ = halo_w(pb, gy, haloOk, haloDx);
        hwin(cw, hw_, lane, W3);
        emit_row(ob + (unsigned)(gy - 1) * W_DIM, S, W3, binsp, s_vf);
        #pragma unroll
        for (int j = 0; j < 4; j++) {
            S[j]     = W3p[j] + (W3[j] - cw[j]);
            W3p[j]   = W3[j];
            binsp[j] = binw[j];
        }
    }

    // ---- row 8 (bottom halo, contributions only) + emit row 7 ----
    {
        const int gy = ybase + 8;
        const bool v = (gy < H_DIM);
        if (v) row_cw(pb + (unsigned)gy * W_DIM, cw);
        else { cw[0] = cw[1] = cw[2] = cw[3] = 0u; }
        const unsigned int hw_ = halo_w(pb, gy, haloOk & v, haloDx);
        hwin(cw, hw_, lane, W3);
        emit_row(ob + (unsigned)(ybase + 7) * W_DIM, S, W3, binsp, s_vf);
    }
}

extern "C" void kernel_launch(void* const* d_in, const int* in_sizes, int n_in,
                              void* d_out, int out_size)
{
    const float* logits    = (const float*)d_in[0];
    const float* val_freqs = (const float*)d_in[1];
    float*       out       = (float*)d_out;

    const int B = in_sizes[0] / (4 * HW);        // 16

    dim3 grid(W_DIM / 128, 16, B);               // 1024 CTAs
    nectar_binning_kernel<<<grid, NTH>>>(logits, val_freqs, out);
}

// round 9
// speedup vs baseline: 1.1829x; 1.0112x over previous
#include <cuda_runtime.h>

// NECTAR binning — warp-streaming bands, fully unrolled rows, instruction diet.
// logits [16,4,512,512] f32, val_freqs [4,9,15] f32 -> out [16,4,512,512] f32.

#define H_DIM 512
#define W_DIM 512
#define HW    (H_DIM * W_DIM)
#define NTH   128                    // 4 warps; warp = 128x8 band

__device__ __forceinline__ unsigned int argmax_w(float l0, float l1, float l2, float l3,
                                                 float& m) {
    m = l0; unsigned int w = 1u;
    if (l1 > m) { m = l1; w = 1u << 8;  }
    if (l2 > m) { m = l2; w = 1u << 16; }
    if (l3 > m) { m = l3; w = 1u << 24; }
    return w;
}

// contributions-only row (halo rows -1 / 8)
__device__ __forceinline__ void row_cw(const float* __restrict__ pr, unsigned int cw[4]) {
    const float4 A  = *(const float4*)(pr);
    const float4 Bv = *(const float4*)(pr + HW);
    const float4 Cv = *(const float4*)(pr + 2 * HW);
    const float4 Dv = *(const float4*)(pr + 3 * HW);
    const float p0[4] = {A.x, A.y, A.z, A.w};
    const float p1[4] = {Bv.x, Bv.y, Bv.z, Bv.w};
    const float p2[4] = {Cv.x, Cv.y, Cv.z, Cv.w};
    const float p3[4] = {Dv.x, Dv.y, Dv.z, Dv.w};
    float m;
    #pragma unroll
    for (int j = 0; j < 4; j++)
        cw[j] = argmax_w(p0[j], p1[j], p2[j], p3[j], m);
}

// full row: contributions + packed bins (guarded fast exp)
__device__ __forceinline__ void row_full(const float* __restrict__ pr,
                                         unsigned int cw[4], unsigned int& binw) {
    const float4 A  = *(const float4*)(pr);
    const float4 Bv = *(const float4*)(pr + HW);
    const float4 Cv = *(const float4*)(pr + 2 * HW);
    const float4 Dv = *(const float4*)(pr + 3 * HW);
    const float p0[4] = {A.x, A.y, A.z, A.w};
    const float p1[4] = {Bv.x, Bv.y, Bv.z, Bv.w};
    const float p2[4] = {Cv.x, Cv.y, Cv.z, Cv.w};
    const float p3[4] = {Dv.x, Dv.y, Dv.z, Dv.w};
    const float bw = 1.0f / 15.0f;

    int bpx[4];
    #pragma unroll
    for (int j = 0; j < 4; j++) {
        const float l0 = p0[j], l1 = p1[j], l2 = p2[j], l3 = p3[j];
        float m;
        cw[j] = argmax_w(l0, l1, l2, l3, m);

        // fast path (no max-subtract; mathematically identical softmax)
        const float e0 = __expf(l0);
        const float e1 = __expf(l1);
        const float e2 = __expf(l2);
        const float e3 = __expf(l3);
        const float s  = e0 + e1 + e2 + e3;
        const float tt = __fdividef(15.0f, s);
        const float u0 = e0 * tt, u1 = e1 * tt, u2 = e2 * tt, u3 = e3 * tt;
        int b0 = (int)u0, b1 = (int)u1, b2 = (int)u2, b3 = (int)u3;

        const float g = 1e-4f;   // fast-path |u| error bound ~2.3e-5 -> 4x margin
        const float d0 = fminf(fabsf(u0 - rintf(u0)), fabsf(u1 - rintf(u1)));
        const float d1 = fminf(fabsf(u2 - rintf(u2)), fabsf(u3 - rintf(u3)));
        if (fminf(d0, d1) < g) {
            // exact path: bit-validated reference formula
            const float a0 = expf(l0 - m);
            const float a1 = expf(l1 - m);
            const float a2 = expf(l2 - m);
            const float a3 = expf(l3 - m);
            const float as = a0 + a1 + a2 + a3;
            const float at = (1.0f / as) / bw;
            b0 = (int)(a0 * at);
            b1 = (int)(a1 * at);
            b2 = (int)(a2 * at);
            b3 = (int)(a3 * at);
        }
        b0 = b0 > 14 ? 14 : b0;
        b1 = b1 > 14 ? 14 : b1;
        b2 = b2 > 14 ? 14 : b2;
        b3 = b3 > 14 ? 14 : b3;
        // pack 4 bytes with PRMT
        const unsigned int t0 = __byte_perm((unsigned)b0, (unsigned)b1, 0x0040);
        const unsigned int t1 = __byte_perm((unsigned)b2, (unsigned)b3, 0x0040);
        bpx[j] = (int)__byte_perm(t0, t1, 0x5410);
    }
    // binw packs per-j words? No: bins stay per-j; caller needs 4 words. Use array via refs:
    // (kept as 4 words in caller through pointer)
    // This function writes them through binw-extension below.
    // -- replaced by out-params:
    binw = 0; // placeholder overwritten by wrapper (see row_full4)
    ((unsigned int*)&binw)[0] = (unsigned)bpx[0]; // not used
}

// NOTE: wrapper with proper 4-word bins output (avoids the placeholder above)
__device__ __forceinline__ void row_full4(const float* __restrict__ pr,
                                          unsigned int cw[4], unsigned int binw[4]) {
    const float4 A  = *(const float4*)(pr);
    const float4 Bv = *(const float4*)(pr + HW);
    const float4 Cv = *(const float4*)(pr + 2 * HW);
    const float4 Dv = *(const float4*)(pr + 3 * HW);
    const float p0[4] = {A.x, A.y, A.z, A.w};
    const float p1[4] = {Bv.x, Bv.y, Bv.z, Bv.w};
    const float p2[4] = {Cv.x, Cv.y, Cv.z, Cv.w};
    const float p3[4] = {Dv.x, Dv.y, Dv.z, Dv.w};
    const float bw = 1.0f / 15.0f;

    #pragma unroll
    for (int j = 0; j < 4; j++) {
        const float l0 = p0[j], l1 = p1[j], l2 = p2[j], l3 = p3[j];
        float m;
        cw[j] = argmax_w(l0, l1, l2, l3, m);

        const float e0 = __expf(l0);
        const float e1 = __expf(l1);
        const float e2 = __expf(l2);
        const float e3 = __expf(l3);
        const float s  = e0 + e1 + e2 + e3;
        const float tt = __fdividef(15.0f, s);
        const float u0 = e0 * tt, u1 = e1 * tt, u2 = e2 * tt, u3 = e3 * tt;
        int b0 = (int)u0, b1 = (int)u1, b2 = (int)u2, b3 = (int)u3;

        const float g = 1e-4f;
        const float d0 = fminf(fabsf(u0 - rintf(u0)), fabsf(u1 - rintf(u1)));
        const float d1 = fminf(fabsf(u2 - rintf(u2)), fabsf(u3 - rintf(u3)));
        if (fminf(d0, d1) < g) {
            const float a0 = expf(l0 - m);
            const float a1 = expf(l1 - m);
            const float a2 = expf(l2 - m);
            const float a3 = expf(l3 - m);
            const float as = a0 + a1 + a2 + a3;
            const float at = (1.0f / as) / bw;
            b0 = (int)(a0 * at);
            b1 = (int)(a1 * at);
            b2 = (int)(a2 * at);
            b3 = (int)(a3 * at);
        }
        b0 = b0 > 14 ? 14 : b0;
        b1 = b1 > 14 ? 14 : b1;
        b2 = b2 > 14 ? 14 : b2;
        b3 = b3 > 14 ? 14 : b3;
        const unsigned int t0 = __byte_perm((unsigned)b0, (unsigned)b1, 0x0040);
        const unsigned int t1 = __byte_perm((unsigned)b2, (unsigned)b3, 0x0040);
        binw[j] = __byte_perm(t0, t1, 0x5410);
    }
}

__device__ __forceinline__ unsigned int halo_w(const float* __restrict__ pb,
                                               int gy, bool doit, int dx) {
    if (!doit) return 0u;
    const float* hp = pb + (unsigned)gy * W_DIM + dx;
    const float l0 = __ldg(hp);
    const float l1 = __ldg(hp + HW);
    const float l2 = __ldg(hp + 2 * HW);
    const float l3 = __ldg(hp + 3 * HW);
    float m;
    return argmax_w(l0, l1, l2, l3, m);
}

__device__ __forceinline__ void hwin(const unsigned int cw[4], unsigned int hw_,
                                     int lane, unsigned int W3[4]) {
    unsigned int prev = __shfl_up_sync(0xffffffffu, cw[3], 1);
    if (lane == 0)  prev = hw_;
    unsigned int nxt  = __shfl_down_sync(0xffffffffu, cw[0], 1);
    if (lane == 31) nxt = hw_;
    const unsigned int p01 = cw[0] + cw[1];
    const unsigned int p23 = cw[2] + cw[3];
    W3[0] = prev  + p01;
    W3[1] = p01   + cw[2];
    W3[2] = cw[1] + p23;
    W3[3] = p23   + nxt;
}

__device__ __forceinline__ void emit_row(float* __restrict__ po,
                                         const unsigned int S[4], const unsigned int W3[4],
                                         const unsigned int binsp[4],
                                         const float* __restrict__ s_vf) {
    float o0[4], o1[4], o2[4], o3[4];
    #pragma unroll
    for (int j = 0; j < 4; j++) {
        const unsigned int acc = S[j] + W3[j];
        const unsigned int idx = acc * 15u + binsp[j];   // per-byte 15*cnt+bin <= 134
        const float f0 = s_vf[        ( idx         & 0xFFu)];
        const float f1 = s_vf[135u + ((idx >> 8)    & 0xFFu)];
        const float f2 = s_vf[270u + ((idx >> 16)   & 0xFFu)];
        const float f3 = s_vf[405u + ( idx >> 24          )];
        float s = f0 + f1 + f2 + f3;
        s = (s == 0.0f) ? 1.0f : s;
        const float inv = __fdividef(1.0f, s);
        o0[j] = f0 * inv; o1[j] = f1 * inv; o2[j] = f2 * inv; o3[j] = f3 * inv;
    }
    __stcs((float4*)(po),          make_float4(o0[0], o0[1], o0[2], o0[3]));
    __stcs((float4*)(po + HW),     make_float4(o1[0], o1[1], o1[2], o1[3]));
    __stcs((float4*)(po + 2 * HW), make_float4(o2[0], o2[1], o2[2], o2[3]));
    __stcs((float4*)(po + 3 * HW), make_float4(o3[0], o3[1], o3[2], o3[3]));
}

__global__ __launch_bounds__(NTH, 7)
void nectar_binning_kernel(const float* __restrict__ logits,
                           const float* __restrict__ val_freqs,
                           float* __restrict__ out)
{
    __shared__ float s_vf[540];
    const int tid  = threadIdx.x;
    const int lane = tid & 31;
    const int wrp  = tid >> 5;

    for (int i = tid; i < 540; i += NTH) s_vf[i] = val_freqs[i];
    __syncthreads();

    const int x0    = blockIdx.x * 128;
    const int ybase = (blockIdx.y * 4 + wrp) * 8;
    const unsigned int boff = blockIdx.z * 4u * HW;

    const float* pb = logits + boff + (unsigned)x0 + 4u * (unsigned)lane;
    float*       ob = out    + boff + (unsigned)x0 + 4u * (unsigned)lane;

    const bool edgeLane = (lane == 0) | (lane == 31);
    const bool haloOk   = edgeLane & ((lane == 0) ? (x0 > 0) : (x0 + 128 < W_DIM));
    const int  haloDx   = (lane == 0) ? -1 : 4;

    unsigned int cw[4], binw[4], W3p[4], W3[4], S[4], binsp[4];

    // ---- row -1 (top halo, contributions only) ----
    {
        const int gy = ybase - 1;
        const bool v = (gy >= 0);
        if (v) row_cw(pb + (unsigned)gy * W_DIM, cw);
        else { cw[0] = cw[1] = cw[2] = cw[3] = 0u; }
        const unsigned int hw_ = halo_w(pb, gy, haloOk & v, haloDx);
        hwin(cw, hw_, lane, W3p);
    }

    // ---- row 0 (full) ----
    {
        row_full4(pb + (unsigned)ybase * W_DIM, cw, binw);
        const unsigned int hw_ = halo_w(pb, ybase, haloOk, haloDx);
        hwin(cw, hw_, lane, W3);
        #pragma unroll
        for (int j = 0; j < 4; j++) {
            S[j]     = W3p[j] + (W3[j] - cw[j]);
            W3p[j]   = W3[j];
            binsp[j] = binw[j];
        }
    }

    // ---- rows 1..7: FULLY UNROLLED (branch-free; compiler pipelines loads) ----
    #pragma unroll
    for (int r = 1; r <= 7; ++r) {
        const int gy = ybase + r;
        row_full4(pb + (unsigned)gy * W_DIM, cw, binw);
        const unsigned int hw_ = halo_w(pb, gy, haloOk, haloDx);
        hwin(cw, hw_, lane, W3);
        emit_row(ob + (unsigned)(gy - 1) * W_DIM, S, W3, binsp, s_vf);
        #pragma unroll
        for (int j = 0; j < 4; j++) {
            S[j]     = W3p[j] + (W3[j] - cw[j]);
            W3p[j]   = W3[j];
            binsp[j] = binw[j];
        }
    }

    // ---- row 8 (bottom halo, contributions only) + emit row 7 ----
    {
        const int gy = ybase + 8;
        const bool v = (gy < H_DIM);
        if (v) row_cw(pb + (unsigned)gy * W_DIM, cw);
        else { cw[0] = cw[1] = cw[2] = cw[3] = 0u; }
        const unsigned int hw_ = halo_w(pb, gy, haloOk & v, haloDx);
        hwin(cw, hw_, lane, W3);
        emit_row(ob + (unsigned)(ybase + 7) * W_DIM, S, W3, binsp, s_vf);
    }
}

extern "C" void kernel_launch(void* const* d_in, const int* in_sizes, int n_in,
                              void* d_out, int out_size)
{
    const float* logits    = (const float*)d_in[0];
    const float* val_freqs = (const float*)d_in[1];
    float*       out       = (float*)d_out;

    const int B = in_sizes[0] / (4 * HW);        // 16

    dim3 grid(W_DIM / 128, 16, B);               // 1024 CTAs, single wave @7/SM
    nectar_binning_kernel<<<grid, NTH>>>(logits, val_freqs, out);
}

// round 10
// speedup vs baseline: 1.2680x; 1.0719x over previous
#include <cuda_runtime.h>

// NECTAR binning — warp-streaming 128x4 bands (2x parallelism vs 128x8).
// logits [16,4,512,512] f32, val_freqs [4,9,15] f32 -> out [16,4,512,512] f32.

#define H_DIM 512
#define W_DIM 512
#define HW    (H_DIM * W_DIM)
#define NTH   128                    // 4 warps; each warp = 128x4 band
#define BAND  4

__device__ __forceinline__ unsigned int argmax_w(float l0, float l1, float l2, float l3,
                                                 float& m) {
    m = l0; unsigned int w = 1u;
    if (l1 > m) { m = l1; w = 1u << 8;  }
    if (l2 > m) { m = l2; w = 1u << 16; }
    if (l3 > m) { m = l3; w = 1u << 24; }
    return w;
}

// contributions-only row (halo rows)
__device__ __forceinline__ void row_cw(const float* __restrict__ pr, unsigned int cw[4]) {
    const float4 A  = *(const float4*)(pr);
    const float4 Bv = *(const float4*)(pr + HW);
    const float4 Cv = *(const float4*)(pr + 2 * HW);
    const float4 Dv = *(const float4*)(pr + 3 * HW);
    const float p0[4] = {A.x, A.y, A.z, A.w};
    const float p1[4] = {Bv.x, Bv.y, Bv.z, Bv.w};
    const float p2[4] = {Cv.x, Cv.y, Cv.z, Cv.w};
    const float p3[4] = {Dv.x, Dv.y, Dv.z, Dv.w};
    float m;
    #pragma unroll
    for (int j = 0; j < 4; j++)
        cw[j] = argmax_w(p0[j], p1[j], p2[j], p3[j], m);
}

// full row: contributions + packed bins (guarded fast exp)
__device__ __forceinline__ void row_full4(const float* __restrict__ pr,
                                          unsigned int cw[4], unsigned int binw[4]) {
    const float4 A  = *(const float4*)(pr);
    const float4 Bv = *(const float4*)(pr + HW);
    const float4 Cv = *(const float4*)(pr + 2 * HW);
    const float4 Dv = *(const float4*)(pr + 3 * HW);
    const float p0[4] = {A.x, A.y, A.z, A.w};
    const float p1[4] = {Bv.x, Bv.y, Bv.z, Bv.w};
    const float p2[4] = {Cv.x, Cv.y, Cv.z, Cv.w};
    const float p3[4] = {Dv.x, Dv.y, Dv.z, Dv.w};
    const float bw = 1.0f / 15.0f;

    #pragma unroll
    for (int j = 0; j < 4; j++) {
        const float l0 = p0[j], l1 = p1[j], l2 = p2[j], l3 = p3[j];
        float m;
        cw[j] = argmax_w(l0, l1, l2, l3, m);

        // fast path (no max-subtract; mathematically identical softmax)
        const float e0 = __expf(l0);
        const float e1 = __expf(l1);
        const float e2 = __expf(l2);
        const float e3 = __expf(l3);
        const float s  = e0 + e1 + e2 + e3;
        const float tt = __fdividef(15.0f, s);
        const float u0 = e0 * tt, u1 = e1 * tt, u2 = e2 * tt, u3 = e3 * tt;
        int b0 = (int)u0, b1 = (int)u1, b2 = (int)u2, b3 = (int)u3;

        const float g = 1e-4f;   // fast-path |u| error bound ~2.3e-5 -> 4x margin
        const float d0 = fminf(fabsf(u0 - rintf(u0)), fabsf(u1 - rintf(u1)));
        const float d1 = fminf(fabsf(u2 - rintf(u2)), fabsf(u3 - rintf(u3)));
        if (fminf(d0, d1) < g) {
            // exact path: bit-validated reference formula
            const float a0 = expf(l0 - m);
            const float a1 = expf(l1 - m);
            const float a2 = expf(l2 - m);
            const float a3 = expf(l3 - m);
            const float as = a0 + a1 + a2 + a3;
            const float at = (1.0f / as) / bw;
            b0 = (int)(a0 * at);
            b1 = (int)(a1 * at);
            b2 = (int)(a2 * at);
            b3 = (int)(a3 * at);
        }
        b0 = b0 > 14 ? 14 : b0;
        b1 = b1 > 14 ? 14 : b1;
        b2 = b2 > 14 ? 14 : b2;
        b3 = b3 > 14 ? 14 : b3;
        const unsigned int t0 = __byte_perm((unsigned)b0, (unsigned)b1, 0x0040);
        const unsigned int t1 = __byte_perm((unsigned)b2, (unsigned)b3, 0x0040);
        binw[j] = __byte_perm(t0, t1, 0x5410);
    }
}

__device__ __forceinline__ unsigned int halo_w(const float* __restrict__ pb,
                                               int gy, bool doit, int dx) {
    if (!doit) return 0u;
    const float* hp = pb + (unsigned)gy * W_DIM + dx;
    const float l0 = __ldg(hp);
    const float l1 = __ldg(hp + HW);
    const float l2 = __ldg(hp + 2 * HW);
    const float l3 = __ldg(hp + 3 * HW);
    float m;
    return argmax_w(l0, l1, l2, l3, m);
}

__device__ __forceinline__ void hwin(const unsigned int cw[4], unsigned int hw_,
                                     int lane, unsigned int W3[4]) {
    unsigned int prev = __shfl_up_sync(0xffffffffu, cw[3], 1);
    if (lane == 0)  prev = hw_;
    unsigned int nxt  = __shfl_down_sync(0xffffffffu, cw[0], 1);
    if (lane == 31) nxt = hw_;
    const unsigned int p01 = cw[0] + cw[1];
    const unsigned int p23 = cw[2] + cw[3];
    W3[0] = prev  + p01;
    W3[1] = p01   + cw[2];
    W3[2] = cw[1] + p23;
    W3[3] = p23   + nxt;
}

__device__ __forceinline__ void emit_row(float* __restrict__ po,
                                         const unsigned int S[4], const unsigned int W3[4],
                                         const unsigned int binsp[4],
                                         const float* __restrict__ s_vf) {
    float o0[4], o1[4], o2[4], o3[4];
    #pragma unroll
    for (int j = 0; j < 4; j++) {
        const unsigned int acc = S[j] + W3[j];
        const unsigned int idx = acc * 15u + binsp[j];   // per-byte 15*cnt+bin <= 134
        const float f0 = s_vf[        ( idx         & 0xFFu)];
        const float f1 = s_vf[135u + ((idx >> 8)    & 0xFFu)];
        const float f2 = s_vf[270u + ((idx >> 16)   & 0xFFu)];
        const float f3 = s_vf[405u + ( idx >> 24          )];
        float s = f0 + f1 + f2 + f3;
        s = (s == 0.0f) ? 1.0f : s;
        const float inv = __fdividef(1.0f, s);
        o0[j] = f0 * inv; o1[j] = f1 * inv; o2[j] = f2 * inv; o3[j] = f3 * inv;
    }
    __stcs((float4*)(po),          make_float4(o0[0], o0[1], o0[2], o0[3]));
    __stcs((float4*)(po + HW),     make_float4(o1[0], o1[1], o1[2], o1[3]));
    __stcs((float4*)(po + 2 * HW), make_float4(o2[0], o2[1], o2[2], o2[3]));
    __stcs((float4*)(po + 3 * HW), make_float4(o3[0], o3[1], o3[2], o3[3]));
}

__global__ __launch_bounds__(NTH, 8)     // cap regs at 64 -> 8 CTAs/SM possible
void nectar_binning_kernel(const float* __restrict__ logits,
                           const float* __restrict__ val_freqs,
                           float* __restrict__ out)
{
    __shared__ float s_vf[540];
    const int tid  = threadIdx.x;
    const int lane = tid & 31;
    const int wrp  = tid >> 5;

    for (int i = tid; i < 540; i += NTH) s_vf[i] = val_freqs[i];
    __syncthreads();

    const int x0    = blockIdx.x * 128;
    const int ybase = (blockIdx.y * 4 + wrp) * BAND;
    const unsigned int boff = blockIdx.z * 4u * HW;

    const float* pb = logits + boff + (unsigned)x0 + 4u * (unsigned)lane;
    float*       ob = out    + boff + (unsigned)x0 + 4u * (unsigned)lane;

    const bool edgeLane = (lane == 0) | (lane == 31);
    const bool haloOk   = edgeLane & ((lane == 0) ? (x0 > 0) : (x0 + 128 < W_DIM));
    const int  haloDx   = (lane == 0) ? -1 : 4;

    unsigned int cw[4], binw[4], W3p[4], W3[4], S[4], binsp[4];

    // ---- row -1 (top halo, contributions only) ----
    {
        const int gy = ybase - 1;
        const bool v = (gy >= 0);
        if (v) row_cw(pb + (unsigned)gy * W_DIM, cw);
        else { cw[0] = cw[1] = cw[2] = cw[3] = 0u; }
        const unsigned int hw_ = halo_w(pb, gy, haloOk & v, haloDx);
        hwin(cw, hw_, lane, W3p);
    }

    // ---- row 0 (full) ----
    {
        row_full4(pb + (unsigned)ybase * W_DIM, cw, binw);
        const unsigned int hw_ = halo_w(pb, ybase, haloOk, haloDx);
        hwin(cw, hw_, lane, W3);
        #pragma unroll
        for (int j = 0; j < 4; j++) {
            S[j]     = W3p[j] + (W3[j] - cw[j]);
            W3p[j]   = W3[j];
            binsp[j] = binw[j];
        }
    }

    // ---- rows 1..BAND-1 (full; each emits row r-1), fully unrolled ----
    #pragma unroll
    for (int r = 1; r <= BAND - 1; ++r) {
        const int gy = ybase + r;
        row_full4(pb + (unsigned)gy * W_DIM, cw, binw);
        const unsigned int hw_ = halo_w(pb, gy, haloOk, haloDx);
        hwin(cw, hw_, lane, W3);
        emit_row(ob + (unsigned)(gy - 1) * W_DIM, S, W3, binsp, s_vf);
        #pragma unroll
        for (int j = 0; j < 4; j++) {
            S[j]     = W3p[j] + (W3[j] - cw[j]);
            W3p[j]   = W3[j];
            binsp[j] = binw[j];
        }
    }

    // ---- row BAND (bottom halo, contributions only) + emit row BAND-1 ----
    {
        const int gy = ybase + BAND;
        const bool v = (gy < H_DIM);
        if (v) row_cw(pb + (unsigned)gy * W_DIM, cw);
        else { cw[0] = cw[1] = cw[2] = cw[3] = 0u; }
        const unsigned int hw_ = halo_w(pb, gy, haloOk & v, haloDx);
        hwin(cw, hw_, lane, W3);
        emit_row(ob + (unsigned)(ybase + BAND - 1) * W_DIM, S, W3, binsp, s_vf);
    }
}

extern "C" void kernel_launch(void* const* d_in, const int* in_sizes, int n_in,
                              void* d_out, int out_size)
{
    const float* logits    = (const float*)d_in[0];
    const float* val_freqs = (const float*)d_in[1];
    float*       out       = (float*)d_out;

    const int B = in_sizes[0] / (4 * HW);            // 16

    dim3 grid(W_DIM / 128, H_DIM / (4 * BAND), B);   // 4 x 32 x 16 = 2048 CTAs
    nectar_binning_kernel<<<grid, NTH>>>(logits, val_freqs, out);
}